// round 14
// baseline (speedup 1.0000x reference)
#include <cuda_runtime.h>

#define NN 512   // nodes
#define NE 512   // edges
#define D  128   // emb dim
#define H  256   // hidden
#define NI 8192  // incidences

// ---------------- scratch (no allocations allowed) ----------------
__device__ float g_eSum[NE * D];
__device__ float g_eCnt[NE];
__device__ float g_hX [NN * H];   // a[n,h] = W2[h]*hX[n,h]
__device__ float g_hEb[NE * H];   // b[m,h] = W2[h]*(hEb[m,h]+b1[h])
__device__ float g_P[NN];         // sum_h a[n,h]
__device__ float g_Q[NE];         // sum_h b[m,h]
__device__ float g_sig[H];        // 0.5*sign(W2[h])  (+0.5 at 0)
__device__ int   g_mode;          // 1 = indices are int64, 0 = int32

typedef unsigned long long ull;

// acc += |lo(a+b)|*sgLo + |hi(a+b)|*sgHi      (FADD2 + 2 FFMA with |.| folded)
__device__ __forceinline__ void absacc(float& acc, ull a, ull b, float sgLo, float sgHi) {
    asm("{\n\t"
        ".reg .f32 lo, hi, al, ah;\n\t"
        ".reg .b64 t;\n\t"
        "add.rn.f32x2 t, %1, %2;\n\t"
        "mov.b64 {lo, hi}, t;\n\t"
        "abs.f32 al, lo;\n\t"
        "abs.f32 ah, hi;\n\t"
        "fma.rn.f32 %0, al, %3, %0;\n\t"
        "fma.rn.f32 %0, ah, %4, %0;\n\t"
        "}"
        : "+f"(acc) : "l"(a), "l"(b), "f"(sgLo), "f"(sgHi));
}

__device__ __forceinline__ void redadd(float* p, float v) {
    asm volatile("red.global.add.f32 [%0], %1;" :: "l"(p), "f"(v) : "memory");
}

// ---------------- K0: zero scratch + sig + warp-parallel dtype detect ----------------
__global__ void k_zero_detect(const void* __restrict__ Ep, const float* __restrict__ W2) {
    int i = blockIdx.x * 256 + threadIdx.x;          // 66*256 covers 16768 float4
    float4 z = make_float4(0.f, 0.f, 0.f, 0.f);
    if (i < 16384) {
        ((float4*)g_eSum)[i] = z;
    } else if (i < 16512) {
        ((float4*)g_eCnt)[i - 16384] = z;
    } else if (i < 16640) {
        ((float4*)g_P)[i - 16512] = z;
    } else if (i < 16768) {
        ((float4*)g_Q)[i - 16640] = z;
    }
    if (blockIdx.x == 0 && threadIdx.x < H) {
        g_sig[threadIdx.x] = (W2[threadIdx.x] >= 0.0f) ? 0.5f : -0.5f;
    }
    if (blockIdx.x == 1 && threadIdx.x < 32) {
        long long v = ((const long long*)Ep)[threadIdx.x];
        unsigned bad = __ballot_sync(0xFFFFFFFFu, v < 0 || v >= (long long)NE);
        if (threadIdx.x == 0) g_mode = (bad == 0u) ? 1 : 0;
    }
}

// ---------------- K1: scatter-sum + counts (vector RED) ----------------
__global__ void k_scatter(const float* __restrict__ X,
                          const void* __restrict__ Vp,
                          const void* __restrict__ Ep) {
    int gid = blockIdx.x * 256 + threadIdx.x;        // NI*32 threads
    int inc = gid >> 5;
    int q   = gid & 31;
    int v, e;
    if (g_mode) {
        v = (int)((const long long*)Vp)[inc];
        e = (int)((const long long*)Ep)[inc];
    } else {
        v = ((const int*)Vp)[inc];
        e = ((const int*)Ep)[inc];
    }
    float4 f = *(const float4*)(X + v * D + q * 4);
    float* dst = g_eSum + e * D + q * 4;
    asm volatile("red.global.add.v4.f32 [%0], {%1, %2, %3, %4};"
                 :: "l"(dst), "f"(f.x), "f"(f.y), "f"(f.z), "f"(f.w) : "memory");
    if (q == 0)
        asm volatile("red.global.add.f32 [%0], %1;"
                     :: "l"(&g_eCnt[e]), "f"(1.0f) : "memory");
}

// ---------------- K2: fused scaled GEMM for a and b (+ P/Q) ----------------
// Rows 0..511   : a[n,h] = (X @ W1[:,:128].T)[n,h] * W2[h];        P[n]=sum_h a
// Rows 512..1023: b[m,h] = ((eX)@W1[:,128:].T + b1)[m,h] * W2[h];  Q[m]=sum_h b
__global__ void __launch_bounds__(256) k_gemm(const float* __restrict__ X,
                                              const float* __restrict__ W1,
                                              const float* __restrict__ b1,
                                              const float* __restrict__ W2) {
    __shared__ float sA[32 * 36];   // [k][row], ld=36
    __shared__ float sB[32 * 68];   // [k][h],  ld=68
    int tid = threadIdx.x;
    int tx = tid & 15, ty = tid >> 4;
    int h0 = blockIdx.x * 64;
    int r0 = blockIdx.y * 32;
    bool isX = (r0 < NN);
    int koff = isX ? 0 : D;

    float acc[2][4];
    #pragma unroll
    for (int i = 0; i < 2; i++)
        #pragma unroll
        for (int j = 0; j < 4; j++) acc[i][j] = 0.0f;

    for (int k0 = 0; k0 < D; k0 += 32) {
        __syncthreads();
        {   // A: 32 rows x 32 k = 256 float4
            int kq = tid & 7;
            int r  = tid >> 3;
            int gr = r0 + r;
            float4 f;
            if (isX) {
                f = *(const float4*)(X + gr * D + k0 + kq * 4);
            } else {
                f = *(const float4*)(g_eSum + (gr - NN) * D + k0 + kq * 4);
                float c = g_eCnt[gr - NN];
                float s = 1.0f / fmaxf(c, 1.0f);
                f.x *= s; f.y *= s; f.z *= s; f.w *= s;
            }
            sA[(kq * 4 + 0) * 36 + r] = f.x;
            sA[(kq * 4 + 1) * 36 + r] = f.y;
            sA[(kq * 4 + 2) * 36 + r] = f.z;
            sA[(kq * 4 + 3) * 36 + r] = f.w;
        }
        #pragma unroll
        for (int i = 0; i < 2; i++) {  // B: 64 h x 32 k = 512 float4
            int lin = tid + 256 * i;
            int kq = lin & 7;
            int hr = lin >> 3;
            float4 g = *(const float4*)(W1 + (h0 + hr) * (2 * D) + koff + k0 + kq * 4);
            sB[(kq * 4 + 0) * 68 + hr] = g.x;
            sB[(kq * 4 + 1) * 68 + hr] = g.y;
            sB[(kq * 4 + 2) * 68 + hr] = g.z;
            sB[(kq * 4 + 3) * 68 + hr] = g.w;
        }
        __syncthreads();

        #pragma unroll
        for (int kk = 0; kk < 32; kk++) {
            float2 a2 = *(float2*)&sA[kk * 36 + 2 * ty];
            float4 b4 = *(float4*)&sB[kk * 68 + 4 * tx];
            float a[2] = {a2.x, a2.y};
            float b[4] = {b4.x, b4.y, b4.z, b4.w};
            #pragma unroll
            for (int i = 0; i < 2; i++)
                #pragma unroll
                for (int j = 0; j < 4; j++)
                    acc[i][j] = fmaf(a[i], b[j], acc[i][j]);
        }
    }

    float w2v[4], b1v[4];
    #pragma unroll
    for (int j = 0; j < 4; j++) {
        w2v[j] = W2[h0 + 4 * tx + j];
        b1v[j] = isX ? 0.0f : b1[h0 + 4 * tx + j];
    }
    #pragma unroll
    for (int i = 0; i < 2; i++) {
        int gr = r0 + 2 * ty + i;
        float p = 0.0f;
        #pragma unroll
        for (int j = 0; j < 4; j++) {
            float val = (acc[i][j] + b1v[j]) * w2v[j];
            if (isX) g_hX[gr * H + h0 + 4 * tx + j] = val;
            else     g_hEb[(gr - NN) * H + h0 + 4 * tx + j] = val;
            p += val;
        }
        if (isX) redadd(&g_P[gr], p);
        else     redadd(&g_Q[gr - NN], p);
    }
}

// ---------------- K3: abs-identity epilogue, 4n x 2m thread tile ----------------
// logits[n,m] = 0.5*(P[n]+Q[m]) + sum_h sig_h * |a[n,h]+b[m,h]| + b2
// CTA tile 32n x 16m, 128 threads in two 64-thread warp-groups (h-split),
// 8x8 lane layout -> X loads 4-addr/warp, E loads 8-addr/warp (1 wavefront each).
// Grid (32, 16) = 512 CTAs -> ~3.5 CTAs/SM.
__global__ void __launch_bounds__(128) k_epi(const float* __restrict__ b2,
                                             float* __restrict__ out) {
    __shared__ float sX[2][32 * 68];   // [wg][n][h-chunk], ld=68
    __shared__ float sE[2][16 * 68];   // [wg][m][h-chunk]
    __shared__ float sS[2][64];        // sig chunk
    __shared__ float sRed[512];        // wg1 partials
    int tid = threadIdx.x;
    int wg = tid >> 6;                 // warp-group 0/1 (64 threads each)
    int wtid = tid & 63;
    int tx = wtid & 7;                 // m = m0 + tx + 8j   (j 0..1)
    int ty = wtid >> 3;                // n = n0 + ty + 8i   (i 0..3)
    int m0 = blockIdx.x * 16;
    int n0 = blockIdx.y * 32;
    int hbase = wg * 128;              // this wg's h range

    float* sXw = sX[wg];
    float* sEw = sE[wg];
    float* sSw = sS[wg];

    #define WGBAR() asm volatile("bar.sync %0, 64;" :: "r"(wg + 1) : "memory")

    float acc[4][2];
    #pragma unroll
    for (int i = 0; i < 4; i++)
        #pragma unroll
        for (int j = 0; j < 2; j++) acc[i][j] = 0.0f;

    int xoff[4], eoff[2];
    #pragma unroll
    for (int i = 0; i < 4; i++) xoff[i] = (ty + 8 * i) * 68;
    #pragma unroll
    for (int j = 0; j < 2; j++) eoff[j] = (tx + 8 * j) * 68;

    #pragma unroll 1
    for (int c = 0; c < 2; c++) {
        int hc = hbase + 64 * c;
        WGBAR();                       // prior chunk's reads complete
        #pragma unroll
        for (int i = 0; i < 8; i++) {  // sX: 32 rows x 16 quads, 8/thread
            int lin = wtid + 64 * i;
            int q = lin & 15, r = lin >> 4;
            *(float4*)&sXw[r * 68 + 4 * q] =
                *(const float4*)(g_hX + (n0 + r) * H + hc + 4 * q);
        }
        #pragma unroll
        for (int i = 0; i < 4; i++) {  // sE: 16 rows x 16 quads, 4/thread
            int lin = wtid + 64 * i;
            int q = lin & 15, r = lin >> 4;
            *(float4*)&sEw[r * 68 + 4 * q] =
                *(const float4*)(g_hEb + (m0 + r) * H + hc + 4 * q);
        }
        if (wtid < 16)
            *(float4*)&sSw[4 * wtid] = *(const float4*)(g_sig + hc + 4 * wtid);
        WGBAR();

        #pragma unroll
        for (int it = 0; it < 16; it++) {
            int h = 4 * it;
            float4 S = *(const float4*)&sSw[h];
            ulonglong2 Xb[4], Eb[2];
            #pragma unroll
            for (int i = 0; i < 4; i++)
                Xb[i] = *(const ulonglong2*)&sXw[xoff[i] + h];
            #pragma unroll
            for (int j = 0; j < 2; j++)
                Eb[j] = *(const ulonglong2*)&sEw[eoff[j] + h];
            #pragma unroll
            for (int i = 0; i < 4; i++)
                #pragma unroll
                for (int j = 0; j < 2; j++) {
                    absacc(acc[i][j], Xb[i].x, Eb[j].x, S.x, S.y);
                    absacc(acc[i][j], Xb[i].y, Eb[j].y, S.z, S.w);
                }
        }
    }
    #undef WGBAR

    // combine warp-group partials: wg1 -> smem, wg0 adds + rank-1 + sigmoid
    if (wg == 1) {
        #pragma unroll
        for (int i = 0; i < 4; i++)
            *(float2*)&sRed[wtid * 8 + 2 * i] = make_float2(acc[i][0], acc[i][1]);
    }
    __syncthreads();
    if (wg == 0) {
        float pn[4], qm[2];
        #pragma unroll
        for (int i = 0; i < 4; i++) pn[i] = g_P[n0 + ty + 8 * i];
        #pragma unroll
        for (int j = 0; j < 2; j++) qm[j] = g_Q[m0 + tx + 8 * j];
        float b2v = b2[0];
        #pragma unroll
        for (int i = 0; i < 4; i++) {
            float2 o = *(float2*)&sRed[wtid * 8 + 2 * i];
            float tot[2] = {acc[i][0] + o.x, acc[i][1] + o.y};
            int n = n0 + ty + 8 * i;
            #pragma unroll
            for (int j = 0; j < 2; j++) {
                int m = m0 + tx + 8 * j;
                float lg = tot[j] + 0.5f * (pn[i] + qm[j]) + b2v;
                float p = 1.0f / (1.0f + __expf(-lg));
                p = fminf(fmaxf(p, 1e-6f), 1.0f - 1e-6f);
                out[n * NE + m] = p;
            }
        }
    }
}

// ---------------- launch ----------------
extern "C" void kernel_launch(void* const* d_in, const int* in_sizes, int n_in,
                              void* d_out, int out_size) {
    const float* X  = (const float*)d_in[0];
    const void*  V  = d_in[1];
    const void*  E  = d_in[2];
    const float* W1 = (const float*)d_in[3];
    const float* b1 = (const float*)d_in[4];
    const float* W2 = (const float*)d_in[5];
    const float* b2 = (const float*)d_in[6];
    float* out = (float*)d_out;

    k_zero_detect<<<66, 256>>>(E, W2);                            // zero + sig + detect
    k_scatter<<<(NI * 32) / 256, 256>>>(X, V, E);                 // 1024 blocks
    k_gemm<<<dim3(H / 64, (NN + NE) / 32), 256>>>(X, W1, b1, W2); // (4,32) = 128 CTAs
    k_epi<<<dim3(NE / 16, NN / 32), 128>>>(b2, out);              // (32,16) = 512 CTAs
}

// round 15
// speedup vs baseline: 1.0743x; 1.0743x over previous
#include <cuda_runtime.h>

#define NN 512   // nodes
#define NE 512   // edges
#define D  128   // emb dim
#define H  256   // hidden
#define NI 8192  // incidences

// ---------------- scratch (no allocations allowed) ----------------
__device__ float g_eSum[NE * D];
__device__ float g_eCnt[NE];
__device__ float g_hX [NN * H];   // a[n,h] = W2[h]*hX[n,h]
__device__ float g_hEb[NE * H];   // b[m,h] = W2[h]*(hEb[m,h]+b1[h])
__device__ float g_P[NN];         // sum_h a[n,h]
__device__ float g_Q[NE];         // sum_h b[m,h]
__device__ float g_sig[H];        // 0.5*sign(W2[h])  (+0.5 at 0)
__device__ int   g_mode;          // 1 = indices are int64, 0 = int32

typedef unsigned long long ull;

// acc += |lo(a+b)|*sgLo + |hi(a+b)|*sgHi      (FADD2 + 2 FFMA with |.| folded)
__device__ __forceinline__ void absacc(float& acc, ull a, ull b, float sgLo, float sgHi) {
    asm("{\n\t"
        ".reg .f32 lo, hi, al, ah;\n\t"
        ".reg .b64 t;\n\t"
        "add.rn.f32x2 t, %1, %2;\n\t"
        "mov.b64 {lo, hi}, t;\n\t"
        "abs.f32 al, lo;\n\t"
        "abs.f32 ah, hi;\n\t"
        "fma.rn.f32 %0, al, %3, %0;\n\t"
        "fma.rn.f32 %0, ah, %4, %0;\n\t"
        "}"
        : "+f"(acc) : "l"(a), "l"(b), "f"(sgLo), "f"(sgHi));
}

__device__ __forceinline__ void redadd(float* p, float v) {
    asm volatile("red.global.add.f32 [%0], %1;" :: "l"(p), "f"(v) : "memory");
}

// ---------------- K0: zero scratch + sig + warp-parallel dtype detect ----------------
__global__ void k_zero_detect(const void* __restrict__ Ep, const float* __restrict__ W2) {
    int i = blockIdx.x * 256 + threadIdx.x;          // 66*256 covers 16768 float4
    float4 z = make_float4(0.f, 0.f, 0.f, 0.f);
    if (i < 16384) {
        ((float4*)g_eSum)[i] = z;
    } else if (i < 16512) {
        ((float4*)g_eCnt)[i - 16384] = z;
    } else if (i < 16640) {
        ((float4*)g_P)[i - 16512] = z;
    } else if (i < 16768) {
        ((float4*)g_Q)[i - 16640] = z;
    }
    if (blockIdx.x == 0 && threadIdx.x < H) {
        g_sig[threadIdx.x] = (W2[threadIdx.x] >= 0.0f) ? 0.5f : -0.5f;
    }
    if (blockIdx.x == 1 && threadIdx.x < 32) {
        long long v = ((const long long*)Ep)[threadIdx.x];
        unsigned bad = __ballot_sync(0xFFFFFFFFu, v < 0 || v >= (long long)NE);
        if (threadIdx.x == 0) g_mode = (bad == 0u) ? 1 : 0;
    }
}

// ---------------- K1: scatter-sum + counts (vector RED) ----------------
__global__ void k_scatter(const float* __restrict__ X,
                          const void* __restrict__ Vp,
                          const void* __restrict__ Ep) {
    int gid = blockIdx.x * 256 + threadIdx.x;        // NI*32 threads
    int inc = gid >> 5;
    int q   = gid & 31;
    int v, e;
    if (g_mode) {
        v = (int)((const long long*)Vp)[inc];
        e = (int)((const long long*)Ep)[inc];
    } else {
        v = ((const int*)Vp)[inc];
        e = ((const int*)Ep)[inc];
    }
    float4 f = *(const float4*)(X + v * D + q * 4);
    float* dst = g_eSum + e * D + q * 4;
    asm volatile("red.global.add.v4.f32 [%0], {%1, %2, %3, %4};"
                 :: "l"(dst), "f"(f.x), "f"(f.y), "f"(f.z), "f"(f.w) : "memory");
    if (q == 0)
        asm volatile("red.global.add.f32 [%0], %1;"
                     :: "l"(&g_eCnt[e]), "f"(1.0f) : "memory");
}

// ---------------- K2: fused scaled GEMM for a and b (+ P/Q) ----------------
// Rows 0..511   : a[n,h] = (X @ W1[:,:128].T)[n,h] * W2[h];        P[n]=sum_h a
// Rows 512..1023: b[m,h] = ((eX)@W1[:,128:].T + b1)[m,h] * W2[h];  Q[m]=sum_h b
__global__ void __launch_bounds__(256) k_gemm(const float* __restrict__ X,
                                              const float* __restrict__ W1,
                                              const float* __restrict__ b1,
                                              const float* __restrict__ W2) {
    __shared__ float sA[32 * 36];   // [k][row], ld=36
    __shared__ float sB[32 * 68];   // [k][h],  ld=68
    int tid = threadIdx.x;
    int tx = tid & 15, ty = tid >> 4;
    int h0 = blockIdx.x * 64;
    int r0 = blockIdx.y * 32;
    bool isX = (r0 < NN);
    int koff = isX ? 0 : D;

    float acc[2][4];
    #pragma unroll
    for (int i = 0; i < 2; i++)
        #pragma unroll
        for (int j = 0; j < 4; j++) acc[i][j] = 0.0f;

    for (int k0 = 0; k0 < D; k0 += 32) {
        __syncthreads();
        {   // A: 32 rows x 32 k = 256 float4
            int kq = tid & 7;
            int r  = tid >> 3;
            int gr = r0 + r;
            float4 f;
            if (isX) {
                f = *(const float4*)(X + gr * D + k0 + kq * 4);
            } else {
                f = *(const float4*)(g_eSum + (gr - NN) * D + k0 + kq * 4);
                float c = g_eCnt[gr - NN];
                float s = 1.0f / fmaxf(c, 1.0f);
                f.x *= s; f.y *= s; f.z *= s; f.w *= s;
            }
            sA[(kq * 4 + 0) * 36 + r] = f.x;
            sA[(kq * 4 + 1) * 36 + r] = f.y;
            sA[(kq * 4 + 2) * 36 + r] = f.z;
            sA[(kq * 4 + 3) * 36 + r] = f.w;
        }
        #pragma unroll
        for (int i = 0; i < 2; i++) {  // B: 64 h x 32 k = 512 float4
            int lin = tid + 256 * i;
            int kq = lin & 7;
            int hr = lin >> 3;
            float4 g = *(const float4*)(W1 + (h0 + hr) * (2 * D) + koff + k0 + kq * 4);
            sB[(kq * 4 + 0) * 68 + hr] = g.x;
            sB[(kq * 4 + 1) * 68 + hr] = g.y;
            sB[(kq * 4 + 2) * 68 + hr] = g.z;
            sB[(kq * 4 + 3) * 68 + hr] = g.w;
        }
        __syncthreads();

        #pragma unroll
        for (int kk = 0; kk < 32; kk++) {
            float2 a2 = *(float2*)&sA[kk * 36 + 2 * ty];
            float4 b4 = *(float4*)&sB[kk * 68 + 4 * tx];
            float a[2] = {a2.x, a2.y};
            float b[4] = {b4.x, b4.y, b4.z, b4.w};
            #pragma unroll
            for (int i = 0; i < 2; i++)
                #pragma unroll
                for (int j = 0; j < 4; j++)
                    acc[i][j] = fmaf(a[i], b[j], acc[i][j]);
        }
    }

    float w2v[4], b1v[4];
    #pragma unroll
    for (int j = 0; j < 4; j++) {
        w2v[j] = W2[h0 + 4 * tx + j];
        b1v[j] = isX ? 0.0f : b1[h0 + 4 * tx + j];
    }
    #pragma unroll
    for (int i = 0; i < 2; i++) {
        int gr = r0 + 2 * ty + i;
        float p = 0.0f;
        #pragma unroll
        for (int j = 0; j < 4; j++) {
            float val = (acc[i][j] + b1v[j]) * w2v[j];
            if (isX) g_hX[gr * H + h0 + 4 * tx + j] = val;
            else     g_hEb[(gr - NN) * H + h0 + 4 * tx + j] = val;
            p += val;
        }
        if (isX) redadd(&g_P[gr], p);
        else     redadd(&g_Q[gr - NN], p);
    }
}

// ---------------- K3: abs-identity epilogue, double-buffered ----------------
// logits[n,m] = 0.5*(P[n]+Q[m]) + sum_h sig_h * |a[n,h]+b[m,h]| + b2
// CTA tile 32n x 16m, 128 threads in two 64-thread warp-groups (h-split),
// thread tile 4n x 2m on 8x8 lanes; explicit 2-stage LDS pipeline.
// Grid (32, 16) = 512 CTAs.
__global__ void __launch_bounds__(128) k_epi(const float* __restrict__ b2,
                                             float* __restrict__ out) {
    __shared__ float sX[2][32 * 68];   // [wg][n][h-chunk], ld=68
    __shared__ float sE[2][16 * 68];   // [wg][m][h-chunk]
    __shared__ float sS[2][64];        // sig chunk
    __shared__ float sRed[512];        // wg1 partials
    int tid = threadIdx.x;
    int wg = tid >> 6;                 // warp-group 0/1 (64 threads each)
    int wtid = tid & 63;
    int tx = wtid & 7;                 // m = m0 + tx + 8j   (j 0..1)
    int ty = wtid >> 3;                // n = n0 + ty + 8i   (i 0..3)
    int m0 = blockIdx.x * 16;
    int n0 = blockIdx.y * 32;
    int hbase = wg * 128;              // this wg's h range

    float* sXw = sX[wg];
    float* sEw = sE[wg];
    float* sSw = sS[wg];

    #define WGBAR() asm volatile("bar.sync %0, 64;" :: "r"(wg + 1) : "memory")

    float acc[4][2];
    #pragma unroll
    for (int i = 0; i < 4; i++)
        #pragma unroll
        for (int j = 0; j < 2; j++) acc[i][j] = 0.0f;

    int xoff[4], eoff[2];
    #pragma unroll
    for (int i = 0; i < 4; i++) xoff[i] = (ty + 8 * i) * 68;
    #pragma unroll
    for (int j = 0; j < 2; j++) eoff[j] = (tx + 8 * j) * 68;

    float4 Sg[2];
    ulonglong2 Xb[2][4], Eb[2][2];
    #define LOADI(s, h)                                                          \
        do {                                                                     \
            Sg[s] = *(const float4*)&sSw[(h)];                                   \
            _Pragma("unroll")                                                    \
            for (int i_ = 0; i_ < 4; i_++)                                       \
                Xb[s][i_] = *(const ulonglong2*)&sXw[xoff[i_] + (h)];            \
            _Pragma("unroll")                                                    \
            for (int j_ = 0; j_ < 2; j_++)                                       \
                Eb[s][j_] = *(const ulonglong2*)&sEw[eoff[j_] + (h)];            \
        } while (0)
    #define COMP(s)                                                              \
        do {                                                                     \
            _Pragma("unroll")                                                    \
            for (int i_ = 0; i_ < 4; i_++)                                       \
                _Pragma("unroll")                                                \
                for (int j_ = 0; j_ < 2; j_++) {                                 \
                    absacc(acc[i_][j_], Xb[s][i_].x, Eb[s][j_].x, Sg[s].x, Sg[s].y); \
                    absacc(acc[i_][j_], Xb[s][i_].y, Eb[s][j_].y, Sg[s].z, Sg[s].w); \
                }                                                                \
        } while (0)

    #pragma unroll 1
    for (int c = 0; c < 2; c++) {
        int hc = hbase + 64 * c;
        WGBAR();                       // prior chunk's reads complete
        #pragma unroll
        for (int i = 0; i < 8; i++) {  // sX: 32 rows x 16 quads, 8/thread
            int lin = wtid + 64 * i;
            int q = lin & 15, r = lin >> 4;
            *(float4*)&sXw[r * 68 + 4 * q] =
                *(const float4*)(g_hX + (n0 + r) * H + hc + 4 * q);
        }
        #pragma unroll
        for (int i = 0; i < 4; i++) {  // sE: 16 rows x 16 quads, 4/thread
            int lin = wtid + 64 * i;
            int q = lin & 15, r = lin >> 4;
            *(float4*)&sEw[r * 68 + 4 * q] =
                *(const float4*)(g_hEb + (m0 + r) * H + hc + 4 * q);
        }
        if (wtid < 16)
            *(float4*)&sSw[4 * wtid] = *(const float4*)(g_sig + hc + 4 * wtid);
        WGBAR();

        LOADI(0, 0);
        #pragma unroll
        for (int it = 0; it < 16; it++) {
            if (it < 15) {
                if (it & 1) LOADI(0, 4 * (it + 1));
                else        LOADI(1, 4 * (it + 1));
            }
            if (it & 1) COMP(1);
            else        COMP(0);
        }
    }
    #undef WGBAR
    #undef LOADI
    #undef COMP

    // combine warp-group partials: wg1 -> smem, wg0 adds + rank-1 + sigmoid
    if (wg == 1) {
        #pragma unroll
        for (int i = 0; i < 4; i++)
            *(float2*)&sRed[wtid * 8 + 2 * i] = make_float2(acc[i][0], acc[i][1]);
    }
    __syncthreads();
    if (wg == 0) {
        float pn[4], qm[2];
        #pragma unroll
        for (int i = 0; i < 4; i++) pn[i] = g_P[n0 + ty + 8 * i];
        #pragma unroll
        for (int j = 0; j < 2; j++) qm[j] = g_Q[m0 + tx + 8 * j];
        float b2v = b2[0];
        #pragma unroll
        for (int i = 0; i < 4; i++) {
            float2 o = *(float2*)&sRed[wtid * 8 + 2 * i];
            float tot[2] = {acc[i][0] + o.x, acc[i][1] + o.y};
            int n = n0 + ty + 8 * i;
            #pragma unroll
            for (int j = 0; j < 2; j++) {
                int m = m0 + tx + 8 * j;
                float lg = tot[j] + 0.5f * (pn[i] + qm[j]) + b2v;
                float p = 1.0f / (1.0f + __expf(-lg));
                p = fminf(fmaxf(p, 1e-6f), 1.0f - 1e-6f);
                out[n * NE + m] = p;
            }
        }
    }
}

// ---------------- launch ----------------
extern "C" void kernel_launch(void* const* d_in, const int* in_sizes, int n_in,
                              void* d_out, int out_size) {
    const float* X  = (const float*)d_in[0];
    const void*  V  = d_in[1];
    const void*  E  = d_in[2];
    const float* W1 = (const float*)d_in[3];
    const float* b1 = (const float*)d_in[4];
    const float* W2 = (const float*)d_in[5];
    const float* b2 = (const float*)d_in[6];
    float* out = (float*)d_out;

    k_zero_detect<<<66, 256>>>(E, W2);                            // zero + sig + detect
    k_scatter<<<(NI * 32) / 256, 256>>>(X, V, E);                 // 1024 blocks
    k_gemm<<<dim3(H / 64, (NN + NE) / 32), 256>>>(X, W1, b1, W2); // (4,32) = 128 CTAs
    k_epi<<<dim3(NE / 16, NN / 32), 128>>>(b2, out);              // (32,16) = 512 CTAs
}